// round 1
// baseline (speedup 1.0000x reference)
#include <cuda_runtime.h>
#include <climits>

// Problem shape is fixed by setup_inputs(): B=8, C=1, H=W=768.
#define BB    8
#define HH    768
#define WW    768
#define HWSZ  (HH * WW)          // 589824
#define NTOT  (BB * HWSZ)        // 4718592

#define ETHREADS 256
#define EBLOCKS  (NTOT / ETHREADS)   // 18432, exact

#define LOSS_BLOCKS  1024
#define LOSS_THREADS 256

// Scratch (static __device__ arrays: no allocation inside kernel_launch).
__device__ int    g_labp[NTOT];   // pred labels / union-find parent (-1 = background)
__device__ int    g_labt[NTOT];   // target labels / union-find parent
__device__ int    g_smin[NTOT];   // per pred-root: min target root seen
__device__ int    g_smax[NTOT];   // per pred-root: max target root seen
__device__ int    g_flag;         // 1 if any pred element < 0 (rescale branch)
__device__ double g_part[LOSS_BLOCKS];

// ---------------------------------------------------------------------------
// Union-find helpers (min-index rooting: deterministic final roots).
// ---------------------------------------------------------------------------
__device__ __forceinline__ int uf_find(const int* L, int x) {
    int p = L[x];
    while (p != x) { x = p; p = L[x]; }
    return x;
}

__device__ __forceinline__ void uf_union(int* L, int a, int b) {
    int ra = uf_find(L, a);
    int rb = uf_find(L, b);
    while (ra != rb) {
        int hi = ra > rb ? ra : rb;
        int lo = ra > rb ? rb : ra;
        int old = atomicMin(&L[hi], lo);
        if (old == hi) break;   // linked hi under lo
        ra = lo;                // hi already had a parent 'old': union(lo, old)
        rb = old;
    }
}

// Exact reference arithmetic for (x + 1.0) * 0.5 without FMA contraction.
__device__ __forceinline__ float resc01(float x) {
    return __fmul_rn(__fadd_rn(x, 1.0f), 0.5f);
}

// ---------------------------------------------------------------------------
// Kernels
// ---------------------------------------------------------------------------
__global__ void k_reset() { g_flag = 0; }

__global__ void k_init(const float* __restrict__ pred) {
    int i = blockIdx.x * blockDim.x + threadIdx.x;
    if (i >= NTOT) return;
    g_smin[i] = INT_MAX;
    g_smax[i] = -1;
    if (pred[i] < 0.0f) g_flag = 1;   // benign race: all writers store 1
}

__global__ void k_labels(const float* __restrict__ pred,
                         const float* __restrict__ target) {
    int i = blockIdx.x * blockDim.x + threadIdx.x;
    if (i >= NTOT) return;
    bool  resc = (g_flag != 0);
    float p  = pred[i];
    float t  = target[i];
    float pp  = resc ? resc01(p) : p;
    float t01 = resc01(t);
    g_labp[i] = (pp  > 0.5f) ? i : -1;
    g_labt[i] = (t01 > 0.5f) ? i : -1;
}

__global__ void k_merge() {
    int i = blockIdx.x * blockDim.x + threadIdx.x;
    if (i >= NTOT) return;
    int local = i % HWSZ;
    int x = local % WW;
    bool has_up = (local >= WW);

    if (g_labp[i] >= 0) {
        if (x > 0   && g_labp[i - 1]  >= 0) uf_union(g_labp, i, i - 1);
        if (has_up  && g_labp[i - WW] >= 0) uf_union(g_labp, i, i - WW);
    }
    if (g_labt[i] >= 0) {
        if (x > 0   && g_labt[i - 1]  >= 0) uf_union(g_labt, i, i - 1);
        if (has_up  && g_labt[i - WW] >= 0) uf_union(g_labt, i, i - WW);
    }
}

// Flatten pred labels to roots; aggregate target-root min/max per pred root.
__global__ void k_flat_agg() {
    int i = blockIdx.x * blockDim.x + threadIdx.x;
    if (i >= NTOT) return;
    int rp = -1, rt = -1;
    if (g_labp[i] >= 0) rp = uf_find(g_labp, i);
    if (g_labt[i] >= 0) rt = uf_find(g_labt, i);
    g_labp[i] = rp;   // safe concurrent shortcut: rp is i's true root
    if (rp >= 0 && rt >= 0) {
        atomicMin(&g_smin[rp], rt);
        atomicMax(&g_smax[rp], rt);
    }
}

__global__ void k_loss(const float* __restrict__ pred,
                       const float* __restrict__ target) {
    __shared__ double sh[LOSS_THREADS];
    bool resc = (g_flag != 0);
    double s = 0.0;
    for (int i = blockIdx.x * blockDim.x + threadIdx.x; i < NTOT;
         i += gridDim.x * blockDim.x) {
        float p  = pred[i];
        float t  = target[i];
        float pp  = resc ? resc01(p) : p;
        float t01 = resc01(t);
        float pl  = fabsf(pp - t01);
        int   rp  = g_labp[i];
        float w   = 1.0f;
        if (rp >= 0 && g_labt[i] < 0 && g_smax[rp] > g_smin[rp]) w = 11.0f;
        s += (double)(pl * w);
    }
    sh[threadIdx.x] = s;
    __syncthreads();
    for (int off = LOSS_THREADS / 2; off > 0; off >>= 1) {
        if (threadIdx.x < off) sh[threadIdx.x] += sh[threadIdx.x + off];
        __syncthreads();
    }
    if (threadIdx.x == 0) g_part[blockIdx.x] = sh[0];
}

__global__ void k_final(float* __restrict__ out) {
    __shared__ double sh[256];
    double s = 0.0;
    for (int i = threadIdx.x; i < LOSS_BLOCKS; i += 256) s += g_part[i];
    sh[threadIdx.x] = s;
    __syncthreads();
    for (int off = 128; off > 0; off >>= 1) {
        if (threadIdx.x < off) sh[threadIdx.x] += sh[threadIdx.x + off];
        __syncthreads();
    }
    if (threadIdx.x == 0) out[0] = (float)(sh[0] / (double)NTOT);
}

// ---------------------------------------------------------------------------
extern "C" void kernel_launch(void* const* d_in, const int* in_sizes, int n_in,
                              void* d_out, int out_size) {
    const float* pred   = (const float*)d_in[0];
    const float* target = (const float*)d_in[1];
    float* out = (float*)d_out;

    k_reset<<<1, 1>>>();
    k_init<<<EBLOCKS, ETHREADS>>>(pred);
    k_labels<<<EBLOCKS, ETHREADS>>>(pred, target);
    k_merge<<<EBLOCKS, ETHREADS>>>();
    k_flat_agg<<<EBLOCKS, ETHREADS>>>();
    k_loss<<<LOSS_BLOCKS, LOSS_THREADS>>>(pred, target);
    k_final<<<1, 256>>>(out);
}

// round 2
// speedup vs baseline: 1.6161x; 1.6161x over previous
#include <cuda_runtime.h>
#include <climits>

// Fixed problem shape: B=8, C=1, H=W=768.
#define BB    8
#define HH    768
#define WW    768
#define HWSZ  (HH * WW)          // 589824
#define NTOT  (BB * HWSZ)        // 4718592

#define TS        32
#define TILES_X   (WW / TS)      // 24
#define TILES_Y   (HH / TS)      // 24

#define EPT   (23 * 768)         // boundary edges of one orientation per image
#define EPI   (2 * EPT)          // 35328 boundary edges per image per mask
#define NEDGE (2 * BB * EPI)     // 565248 total (2 masks)

#define LOSS_BLOCKS  2048
#define LOSS_THREADS 256

// Scratch (static __device__ arrays: allocation-free kernel_launch).
__device__ int    g_labp[NTOT];
__device__ int    g_labt[NTOT];
__device__ int    g_smin[NTOT];
__device__ int    g_smax[NTOT];
__device__ int    g_flag;        // zero-initialized at module load; reset in k_final
__device__ double g_part[LOSS_BLOCKS];

// Exact reference arithmetic for (x + 1.0) * 0.5 without FMA contraction.
__device__ __forceinline__ float resc01(float x) {
    return __fmul_rn(__fadd_rn(x, 1.0f), 0.5f);
}

// ---------------------------------------------------------------------------
// Union-find (min-index rooting; parent <= child invariant)
// ---------------------------------------------------------------------------
__device__ __forceinline__ int uf_find(const int* L, int x) {
    int p = L[x];
    while (p != x) { x = p; p = L[x]; }
    return x;
}

__device__ __forceinline__ void uf_union(int* L, int a, int b) {
    int ra = uf_find(L, a);
    int rb = uf_find(L, b);
    while (ra != rb) {
        int hi = ra > rb ? ra : rb;
        int lo = ra > rb ? rb : ra;
        int old = atomicMin(&L[hi], lo);
        if (old == hi) break;
        ra = lo;
        rb = old;
    }
}

// Find + full path compression (benign races: writes only shorten paths).
__device__ __forceinline__ int uf_findc(int* L, int x) {
    int r = x, p = L[r];
    while (p != r) { r = p; p = L[r]; }
    while (L[x] != r) { int nx = L[x]; L[x] = r; x = nx; }
    return r;
}

// Shared-memory union-find (same logic, smem atomics).
__device__ __forceinline__ int s_find(const int* L, int x) {
    int p = L[x];
    while (p != x) { x = p; p = L[x]; }
    return x;
}

__device__ __forceinline__ void s_union(int* L, int a, int b) {
    int ra = s_find(L, a);
    int rb = s_find(L, b);
    while (ra != rb) {
        int hi = ra > rb ? ra : rb;
        int lo = ra > rb ? rb : ra;
        int old = atomicMin(&L[hi], lo);
        if (old == hi) break;
        ra = lo;
        rb = old;
    }
}

// ---------------------------------------------------------------------------
// Kernels
// ---------------------------------------------------------------------------
__global__ void k_flag(const float4* __restrict__ pred) {
    int i = blockIdx.x * blockDim.x + threadIdx.x;
    float4 v = pred[i];
    bool neg = (v.x < 0.f) | (v.y < 0.f) | (v.z < 0.f) | (v.w < 0.f);
    if (__syncthreads_or(neg) && threadIdx.x == 0) g_flag = 1;
}

// Per 32x32 tile: compute masks, in-tile CCL in shared memory, write labels
// as global-index tile roots. Also initialize smin/smax.
__global__ void k_tile(const float* __restrict__ pred,
                       const float* __restrict__ target) {
    __shared__ int lp[TS * TS];
    __shared__ int lt[TS * TS];
    int lx = threadIdx.x, ly = threadIdx.y;
    int l  = ly * TS + lx;
    int gx = blockIdx.x * TS + lx;
    int gy = blockIdx.y * TS + ly;
    int b  = blockIdx.z;
    int gi = b * HWSZ + gy * WW + gx;

    bool  resc = (g_flag != 0);
    float p = pred[gi];
    float t = target[gi];
    float pp  = resc ? resc01(p) : p;
    float t01 = resc01(t);
    bool mp = pp  > 0.5f;
    bool mt = t01 > 0.5f;

    lp[l] = mp ? l : -1;
    lt[l] = mt ? l : -1;
    g_smin[gi] = INT_MAX;
    g_smax[gi] = -1;
    __syncthreads();

    if (mp) {
        if (lx > 0 && lp[l - 1]  >= 0) s_union(lp, l, l - 1);
        if (ly > 0 && lp[l - TS] >= 0) s_union(lp, l, l - TS);
    }
    if (mt) {
        if (lx > 0 && lt[l - 1]  >= 0) s_union(lt, l, l - 1);
        if (ly > 0 && lt[l - TS] >= 0) s_union(lt, l, l - TS);
    }
    __syncthreads();

    int rp = -1, rt = -1;
    if (mp) {
        int r = s_find(lp, l);
        rp = b * HWSZ + (blockIdx.y * TS + r / TS) * WW + blockIdx.x * TS + r % TS;
    }
    if (mt) {
        int r = s_find(lt, l);
        rt = b * HWSZ + (blockIdx.y * TS + r / TS) * WW + blockIdx.x * TS + r % TS;
    }
    g_labp[gi] = rp;
    g_labt[gi] = rt;
}

// Merge only across tile boundaries (both masks).
__global__ void k_bmerge() {
    int tid = blockIdx.x * blockDim.x + threadIdx.x;
    if (tid >= NEDGE) return;
    int m = tid / (BB * EPI);
    int r = tid % (BB * EPI);
    int b = r / EPI;
    int e = r % EPI;
    int* L = m ? g_labt : g_labp;

    int idx, n;
    if (e < EPT) {                       // vertical boundary: (y,x)-(y,x-1)
        int bi = e / HH, y = e % HH;
        int x  = TS * (bi + 1);
        idx = b * HWSZ + y * WW + x;
        n   = idx - 1;
    } else {                             // horizontal boundary: (y,x)-(y-1,x)
        e -= EPT;
        int bi = e / WW, x = e % WW;
        int y  = TS * (bi + 1);
        idx = b * HWSZ + y * WW + x;
        n   = idx - WW;
    }
    if (L[idx] >= 0 && L[n] >= 0) uf_union(L, idx, n);
}

// Flatten labels to roots (path compression) + per-pred-root target min/max.
__global__ void k_flat_agg() {
    int i = blockIdx.x * blockDim.x + threadIdx.x;
    if (i >= NTOT) return;
    int rp = -1, rt = -1;
    if (g_labp[i] >= 0) rp = uf_findc(g_labp, i);
    if (g_labt[i] >= 0) rt = uf_findc(g_labt, i);
    if (rp >= 0 && rt >= 0) {
        atomicMin(&g_smin[rp], rt);
        atomicMax(&g_smax[rp], rt);
    }
}

__device__ __forceinline__ float px_loss(float p, float t, int rp, int rt, bool resc) {
    float pp  = resc ? resc01(p) : p;
    float t01 = resc01(t);
    float pl  = fabsf(pp - t01);
    float w   = 1.0f;
    if (rp >= 0 && rt < 0 && g_smax[rp] > g_smin[rp]) w = 11.0f;
    return pl * w;
}

__global__ void k_loss(const float4* __restrict__ pred,
                       const float4* __restrict__ target) {
    __shared__ double sh[LOSS_THREADS];
    bool resc = (g_flag != 0);
    const int N4 = NTOT / 4;
    const int4* lp4 = (const int4*)g_labp;
    const int4* lt4 = (const int4*)g_labt;
    double s = 0.0;
    for (int i = blockIdx.x * blockDim.x + threadIdx.x; i < N4;
         i += gridDim.x * blockDim.x) {
        float4 p = pred[i];
        float4 t = target[i];
        int4   a = lp4[i];
        int4   c = lt4[i];
        s += (double)px_loss(p.x, t.x, a.x, c.x, resc);
        s += (double)px_loss(p.y, t.y, a.y, c.y, resc);
        s += (double)px_loss(p.z, t.z, a.z, c.z, resc);
        s += (double)px_loss(p.w, t.w, a.w, c.w, resc);
    }
    sh[threadIdx.x] = s;
    __syncthreads();
    for (int off = LOSS_THREADS / 2; off > 0; off >>= 1) {
        if (threadIdx.x < off) sh[threadIdx.x] += sh[threadIdx.x + off];
        __syncthreads();
    }
    if (threadIdx.x == 0) g_part[blockIdx.x] = sh[0];
}

__global__ void k_final(float* __restrict__ out) {
    __shared__ double sh[256];
    double s = 0.0;
    for (int i = threadIdx.x; i < LOSS_BLOCKS; i += 256) s += g_part[i];
    sh[threadIdx.x] = s;
    __syncthreads();
    for (int off = 128; off > 0; off >>= 1) {
        if (threadIdx.x < off) sh[threadIdx.x] += sh[threadIdx.x + off];
        __syncthreads();
    }
    if (threadIdx.x == 0) {
        out[0] = (float)(sh[0] / (double)NTOT);
        g_flag = 0;   // reset for next run (stream-ordered; zero-init covers run 1)
    }
}

// ---------------------------------------------------------------------------
extern "C" void kernel_launch(void* const* d_in, const int* in_sizes, int n_in,
                              void* d_out, int out_size) {
    const float* pred   = (const float*)d_in[0];
    const float* target = (const float*)d_in[1];
    float* out = (float*)d_out;

    k_flag<<<NTOT / 4 / 256, 256>>>((const float4*)pred);
    k_tile<<<dim3(TILES_X, TILES_Y, BB), dim3(TS, TS)>>>(pred, target);
    k_bmerge<<<(NEDGE + 255) / 256, 256>>>();
    k_flat_agg<<<NTOT / 256, 256>>>();
    k_loss<<<LOSS_BLOCKS, LOSS_THREADS>>>((const float4*)pred, (const float4*)target);
    k_final<<<1, 256>>>(out);
}